// round 4
// baseline (speedup 1.0000x reference)
#include <cuda_runtime.h>
#include <math.h>

#define Bz 8
#define Sz 4096
#define Hz 1024
#define Ez 256
#define Kz 64
#define HQ 256
#define NEGV (-1e30f)

// ---------------- scratch (static __device__, no allocs) ----------------
__device__ float g_tok_scores[Bz * Sz];        // [B,S]
__device__ float g_mx[Bz * Kz];                // per-(b,k) max
__device__ float g_denom[Bz * Kz];             // per-(b,k) sum of exp
__device__ float g_be[(size_t)Bz * Kz * Hz];   // block_embed [B,K,H] (2 MB)
__device__ float g_blk_score[Bz * Kz];         // stage-2 scores

// ======================================================================
// K1: tok_scores = tanh(h @ tok_w1 + b1) @ tok_w2 + b2
// GEMM tile: BM=64, BN=256(=full Hq), BK=16; 256 thr; 8x8 per thread.
// Epilogue fuses tanh + w2-weighted column reduction (warp shfl).
// ======================================================================
__global__ __launch_bounds__(256, 2)
void k1_tok_scores(const float* __restrict__ h,
                   const float* __restrict__ w1,
                   const float* __restrict__ b1,
                   const float* __restrict__ w2,
                   const float* __restrict__ b2) {
    __shared__ float As[16][64];    // [k][m]
    __shared__ float Bs[16][256];   // [k][n]

    const int tid = threadIdx.x;
    const int rowbase = blockIdx.x * 64;
    const int wid = tid >> 5;       // warp id = row group (8 rows)
    const int lane = tid & 31;
    const int c0 = lane * 8;        // this thread's 8 columns

    float acc[8][8];
#pragma unroll
    for (int i = 0; i < 8; i++)
#pragma unroll
        for (int j = 0; j < 8; j++) acc[i][j] = 0.f;

    const int am = tid >> 2;            // 0..63 row within tile
    const int ak = (tid & 3) * 4;       // 0,4,8,12
    const float* hA = h + (size_t)(rowbase + am) * Hz;

    for (int k0 = 0; k0 < Hz; k0 += 16) {
        // load A tile (64x16) — one float4 per thread
        float4 av = *(const float4*)(hA + k0 + ak);
        As[ak + 0][am] = av.x;
        As[ak + 1][am] = av.y;
        As[ak + 2][am] = av.z;
        As[ak + 3][am] = av.w;
        // load B tile (16x256) — four float4 per thread
#pragma unroll
        for (int e = 0; e < 4; e++) {
            int f = tid + e * 256;          // float4 index, 0..1023
            int kk = f >> 6;                // 0..15
            int c4 = (f & 63) * 4;          // 0..252
            *(float4*)&Bs[kk][c4] =
                *(const float4*)(w1 + (size_t)(k0 + kk) * HQ + c4);
        }
        __syncthreads();
#pragma unroll
        for (int kk = 0; kk < 16; kk++) {
            float a[8], b[8];
            *(float4*)&a[0] = *(float4*)&As[kk][wid * 8];
            *(float4*)&a[4] = *(float4*)&As[kk][wid * 8 + 4];
            *(float4*)&b[0] = *(float4*)&Bs[kk][c0];
            *(float4*)&b[4] = *(float4*)&Bs[kk][c0 + 4];
#pragma unroll
            for (int i = 0; i < 8; i++)
#pragma unroll
                for (int j = 0; j < 8; j++)
                    acc[i][j] = fmaf(a[i], b[j], acc[i][j]);
        }
        __syncthreads();
    }

    // epilogue: score_row = sum_c tanh(acc + b1[c]) * w2[c]  (+ b2)
    const float b2v = b2[0];
    float b1v[8], w2v[8];
#pragma unroll
    for (int j = 0; j < 8; j++) { b1v[j] = b1[c0 + j]; w2v[j] = w2[c0 + j]; }
#pragma unroll
    for (int i = 0; i < 8; i++) {
        float p = 0.f;
#pragma unroll
        for (int j = 0; j < 8; j++)
            p += tanhf(acc[i][j] + b1v[j]) * w2v[j];
#pragma unroll
        for (int off = 16; off > 0; off >>= 1)
            p += __shfl_xor_sync(0xffffffffu, p, off);
        if (lane == 0)
            g_tok_scores[rowbase + wid * 8 + i] = p + b2v;
    }
}

// ======================================================================
// K2: per-(b,k) segment max & sum-of-exp over contiguous token range
// ======================================================================
__global__ __launch_bounds__(128)
void k2_seg_stats(const int* __restrict__ mask, const int* __restrict__ bnd) {
    const int bk = blockIdx.x;
    const int b = bk >> 6, k = bk & 63;
    int start = __ldg(&bnd[b * Kz + k]);
    int end = (k == Kz - 1) ? Sz : __ldg(&bnd[b * Kz + k + 1]);
    start = max(0, min(start, Sz));
    end = max(start, min(end, Sz));
    const float* sc = g_tok_scores + b * Sz;
    const int* mk = mask + b * Sz;
    const int tid = threadIdx.x;

    float mx = NEGV;
    for (int s = start + tid; s < end; s += 128)
        if (__ldg(&mk[s]) == 1) mx = fmaxf(mx, sc[s]);
    __shared__ float red[4];
#pragma unroll
    for (int off = 16; off > 0; off >>= 1)
        mx = fmaxf(mx, __shfl_xor_sync(0xffffffffu, mx, off));
    if ((tid & 31) == 0) red[tid >> 5] = mx;
    __syncthreads();
    mx = fmaxf(fmaxf(red[0], red[1]), fmaxf(red[2], red[3]));

    float sum = 0.f;
    for (int s = start + tid; s < end; s += 128)
        if (__ldg(&mk[s]) == 1) sum += expf(sc[s] - mx);
    __shared__ float red2[4];
#pragma unroll
    for (int off = 16; off > 0; off >>= 1)
        sum += __shfl_xor_sync(0xffffffffu, sum, off);
    if ((tid & 31) == 0) red2[tid >> 5] = sum;
    __syncthreads();
    if (tid == 0) {
        g_mx[bk] = mx;
        g_denom[bk] = red2[0] + red2[1] + red2[2] + red2[3];
    }
}

// ======================================================================
// K3: block_embed[b,k,:] = sum_s w[s] * h[b,s,:]   (segmented)
// one block per (b,k); 256 threads, float4 per thread over H=1024
// ======================================================================
__global__ __launch_bounds__(256)
void k3_block_embed(const float* __restrict__ h,
                    const int* __restrict__ mask,
                    const int* __restrict__ bnd) {
    const int bk = blockIdx.x;
    const int b = bk >> 6, k = bk & 63;
    int start = __ldg(&bnd[b * Kz + k]);
    int end = (k == Kz - 1) ? Sz : __ldg(&bnd[b * Kz + k + 1]);
    start = max(0, min(start, Sz));
    end = max(start, min(end, Sz));
    const float mx = g_mx[bk];
    const float den = g_denom[bk];
    const float inv = (den > 0.f) ? 1.f / fmaxf(den, 1e-30f) : 0.f;
    const int tid = threadIdx.x;

    const float* sc = g_tok_scores + b * Sz;
    const int* mk = mask + b * Sz;
    const float* hb = h + (size_t)b * Sz * Hz;

    __shared__ float wts[128];
    float4 acc = make_float4(0.f, 0.f, 0.f, 0.f);

    for (int cs = start; cs < end; cs += 128) {
        const int n = min(128, end - cs);
        if (tid < 128) {
            int s = cs + tid;
            float w = 0.f;
            if (s < end && __ldg(&mk[s]) == 1) w = expf(sc[s] - mx) * inv;
            wts[tid] = w;
        }
        __syncthreads();
        for (int i = 0; i < n; i++) {
            float w = wts[i];
            if (w != 0.f) {
                float4 hv = *(const float4*)(hb + (size_t)(cs + i) * Hz + tid * 4);
                acc.x = fmaf(w, hv.x, acc.x);
                acc.y = fmaf(w, hv.y, acc.y);
                acc.z = fmaf(w, hv.z, acc.z);
                acc.w = fmaf(w, hv.w, acc.w);
            }
        }
        __syncthreads();
    }
    *(float4*)(g_be + (size_t)bk * Hz + tid * 4) = acc;
}

// ======================================================================
// K4: blk_scores = tanh(be @ blk_w1 + b1) @ blk_w2 + b2  (+ validity)
// 4 (b,k) rows per block; thread j owns column j; be rows in smem.
// ======================================================================
__global__ __launch_bounds__(256)
void k4_blk_scores(const float* __restrict__ w1,
                   const float* __restrict__ b1,
                   const float* __restrict__ w2,
                   const float* __restrict__ b2) {
    const int bk0 = blockIdx.x * 4;   // 4 divides 64, so all same batch
    const int j = threadIdx.x;
    __shared__ float bes[4][Hz];      // 16 KB
#pragma unroll
    for (int e = 0; e < 16; e++) {
        int idx = j + e * 256;        // 0..4095
        int r = idx >> 10, d = idx & 1023;
        bes[r][d] = g_be[(size_t)(bk0 + r) * Hz + d];
    }
    __syncthreads();

    float a0 = 0.f, a1 = 0.f, a2 = 0.f, a3 = 0.f;
    for (int d = 0; d < Hz; d++) {
        float w = w1[(size_t)d * HQ + j];
        a0 = fmaf(bes[0][d], w, a0);
        a1 = fmaf(bes[1][d], w, a1);
        a2 = fmaf(bes[2][d], w, a2);
        a3 = fmaf(bes[3][d], w, a3);
    }
    const float b1j = b1[j], w2j = w2[j];
    float v[4];
    v[0] = tanhf(a0 + b1j) * w2j;
    v[1] = tanhf(a1 + b1j) * w2j;
    v[2] = tanhf(a2 + b1j) * w2j;
    v[3] = tanhf(a3 + b1j) * w2j;

    __shared__ float red[4][8];
    const int lane = j & 31, wid = j >> 5;
#pragma unroll
    for (int r = 0; r < 4; r++) {
        float x = v[r];
#pragma unroll
        for (int off = 16; off > 0; off >>= 1)
            x += __shfl_xor_sync(0xffffffffu, x, off);
        if (lane == 0) red[r][wid] = x;
    }
    __syncthreads();
    if (j < 4) {
        float s = 0.f;
#pragma unroll
        for (int w = 0; w < 8; w++) s += red[j][w];
        s += b2[0];
        int bk = bk0 + j;
        g_blk_score[bk] = (g_denom[bk] > 0.f) ? s : NEGV;
    }
}

// ======================================================================
// K5: per batch: softmax over blocks -> func -> out proj -> L2 normalize
// one block per b, 256 threads (thread = output channel e)
// ======================================================================
__global__ __launch_bounds__(256)
void k5_out(const float* __restrict__ out_w,
            const float* __restrict__ out_b,
            float* __restrict__ out) {
    const int b = blockIdx.x;
    const int tid = threadIdx.x;
    __shared__ float bw[Kz];
    __shared__ float func[Hz];
    __shared__ float red[8];

    if (tid == 0) {
        float mx = NEGV;
        for (int k = 0; k < Kz; k++) mx = fmaxf(mx, g_blk_score[b * Kz + k]);
        float s = 0.f;
        for (int k = 0; k < Kz; k++) {
            float e = expf(g_blk_score[b * Kz + k] - mx);
            bw[k] = e;
            s += e;
        }
        float inv = 1.f / s;
        for (int k = 0; k < Kz; k++) bw[k] *= inv;
    }
    __syncthreads();

    // func[d] = sum_k bw[k] * be[b,k,d]
    const float* be = g_be + (size_t)b * Kz * Hz;
    float4 acc = make_float4(0.f, 0.f, 0.f, 0.f);
    for (int k = 0; k < Kz; k++) {
        float w = bw[k];
        float4 v = *(const float4*)(be + (size_t)k * Hz + tid * 4);
        acc.x = fmaf(w, v.x, acc.x);
        acc.y = fmaf(w, v.y, acc.y);
        acc.z = fmaf(w, v.z, acc.z);
        acc.w = fmaf(w, v.w, acc.w);
    }
    *(float4*)&func[tid * 4] = acc;
    __syncthreads();

    // out[e] = func @ out_w[:,e] + out_b[e]
    float o = out_b[tid];
    for (int d = 0; d < Hz; d++)
        o = fmaf(func[d], out_w[(size_t)d * Ez + tid], o);

    // L2 norm across the 256 outputs
    float ss = o * o;
    const int lane = tid & 31, wid = tid >> 5;
#pragma unroll
    for (int off = 16; off > 0; off >>= 1)
        ss += __shfl_xor_sync(0xffffffffu, ss, off);
    if (lane == 0) red[wid] = ss;
    __syncthreads();
    float tot = 0.f;
#pragma unroll
    for (int w = 0; w < 8; w++) tot += red[w];
    float nrm = fmaxf(sqrtf(tot), 1e-12f);
    out[b * Ez + tid] = o / nrm;
}

// ======================================================================
extern "C" void kernel_launch(void* const* d_in, const int* in_sizes, int n_in,
                              void* d_out, int out_size) {
    const float* hidden = (const float*)d_in[0];
    const int* mask = (const int*)d_in[1];
    const int* bnd = (const int*)d_in[2];
    const float* tok_w1 = (const float*)d_in[3];
    const float* tok_b1 = (const float*)d_in[4];
    const float* tok_w2 = (const float*)d_in[5];
    const float* tok_b2 = (const float*)d_in[6];
    const float* blk_w1 = (const float*)d_in[7];
    const float* blk_b1 = (const float*)d_in[8];
    const float* blk_w2 = (const float*)d_in[9];
    const float* blk_b2 = (const float*)d_in[10];
    const float* out_w = (const float*)d_in[11];
    const float* out_b = (const float*)d_in[12];
    float* out = (float*)d_out;

    k1_tok_scores<<<(Bz * Sz) / 64, 256>>>(hidden, tok_w1, tok_b1, tok_w2, tok_b2);
    k2_seg_stats<<<Bz * Kz, 128>>>(mask, bnd);
    k3_block_embed<<<Bz * Kz, 256>>>(hidden, mask, bnd);
    k4_blk_scores<<<(Bz * Kz) / 4, 256>>>(blk_w1, blk_b1, blk_w2, blk_b2);
    k5_out<<<Bz, 256>>>(out_w, out_b, out);
}

// round 5
// speedup vs baseline: 1.1107x; 1.1107x over previous
#include <cuda_runtime.h>
#include <math.h>

#define Bz 8
#define Sz 4096
#define Hz 1024
#define Ez 256
#define Kz 64
#define HQ 256
#define NEGV (-1e30f)
#define K4_CHUNKS 4
#define K4_DCH (Hz / K4_CHUNKS)   // 256

// ---------------- scratch (static __device__, no allocs) ----------------
__device__ float g_tok_scores[Bz * Sz];        // [B,S]
__device__ float g_mx[Bz * Kz];                // per-(b,k) max
__device__ float g_denom[Bz * Kz];             // per-(b,k) sum of exp
__device__ float g_be[(size_t)Bz * Kz * Hz];   // block_embed [B,K,H] (2 MB)
__device__ float g_blk_score[Bz * Kz];         // stage-2 scores
__device__ float g_part[(size_t)K4_CHUNKS * Bz * Kz * HQ];  // k4 split-K partials (2 MB)

// ======================================================================
// K1: tok_scores = tanh(h @ tok_w1 + b1) @ tok_w2 + b2
// GEMM tile: BM=64, BN=256(=full Hq), BK=16; 256 thr; 8x8 per thread.
// Epilogue fuses tanh + w2-weighted column reduction (warp shfl).
// ======================================================================
__global__ __launch_bounds__(256, 2)
void k1_tok_scores(const float* __restrict__ h,
                   const float* __restrict__ w1,
                   const float* __restrict__ b1,
                   const float* __restrict__ w2,
                   const float* __restrict__ b2) {
    __shared__ float As[16][64];    // [k][m]
    __shared__ float Bs[16][256];   // [k][n]

    const int tid = threadIdx.x;
    const int rowbase = blockIdx.x * 64;
    const int wid = tid >> 5;       // warp id = row group (8 rows)
    const int lane = tid & 31;
    const int c0 = lane * 8;        // this thread's 8 columns

    float acc[8][8];
#pragma unroll
    for (int i = 0; i < 8; i++)
#pragma unroll
        for (int j = 0; j < 8; j++) acc[i][j] = 0.f;

    const int am = tid >> 2;            // 0..63 row within tile
    const int ak = (tid & 3) * 4;       // 0,4,8,12
    const float* hA = h + (size_t)(rowbase + am) * Hz;

    for (int k0 = 0; k0 < Hz; k0 += 16) {
        // load A tile (64x16) — one float4 per thread
        float4 av = *(const float4*)(hA + k0 + ak);
        As[ak + 0][am] = av.x;
        As[ak + 1][am] = av.y;
        As[ak + 2][am] = av.z;
        As[ak + 3][am] = av.w;
        // load B tile (16x256) — four float4 per thread
#pragma unroll
        for (int e = 0; e < 4; e++) {
            int f = tid + e * 256;          // float4 index, 0..1023
            int kk = f >> 6;                // 0..15
            int c4 = (f & 63) * 4;          // 0..252
            *(float4*)&Bs[kk][c4] =
                *(const float4*)(w1 + (size_t)(k0 + kk) * HQ + c4);
        }
        __syncthreads();
#pragma unroll
        for (int kk = 0; kk < 16; kk++) {
            float a[8], b[8];
            *(float4*)&a[0] = *(float4*)&As[kk][wid * 8];
            *(float4*)&a[4] = *(float4*)&As[kk][wid * 8 + 4];
            *(float4*)&b[0] = *(float4*)&Bs[kk][c0];
            *(float4*)&b[4] = *(float4*)&Bs[kk][c0 + 4];
#pragma unroll
            for (int i = 0; i < 8; i++)
#pragma unroll
                for (int j = 0; j < 8; j++)
                    acc[i][j] = fmaf(a[i], b[j], acc[i][j]);
        }
        __syncthreads();
    }

    // epilogue: score_row = sum_c tanh(acc + b1[c]) * w2[c]  (+ b2)
    const float b2v = b2[0];
    float b1v[8], w2v[8];
#pragma unroll
    for (int j = 0; j < 8; j++) { b1v[j] = b1[c0 + j]; w2v[j] = w2[c0 + j]; }
#pragma unroll
    for (int i = 0; i < 8; i++) {
        float p = 0.f;
#pragma unroll
        for (int j = 0; j < 8; j++)
            p += tanhf(acc[i][j] + b1v[j]) * w2v[j];
#pragma unroll
        for (int off = 16; off > 0; off >>= 1)
            p += __shfl_xor_sync(0xffffffffu, p, off);
        if (lane == 0)
            g_tok_scores[rowbase + wid * 8 + i] = p + b2v;
    }
}

// ======================================================================
// K2: per-(b,k) segment max & sum-of-exp over contiguous token range
// ======================================================================
__global__ __launch_bounds__(128)
void k2_seg_stats(const int* __restrict__ mask, const int* __restrict__ bnd) {
    const int bk = blockIdx.x;
    const int b = bk >> 6, k = bk & 63;
    int start = __ldg(&bnd[b * Kz + k]);
    int end = (k == Kz - 1) ? Sz : __ldg(&bnd[b * Kz + k + 1]);
    start = max(0, min(start, Sz));
    end = max(start, min(end, Sz));
    const float* sc = g_tok_scores + b * Sz;
    const int* mk = mask + b * Sz;
    const int tid = threadIdx.x;

    float mx = NEGV;
    for (int s = start + tid; s < end; s += 128)
        if (__ldg(&mk[s]) == 1) mx = fmaxf(mx, sc[s]);
    __shared__ float red[4];
#pragma unroll
    for (int off = 16; off > 0; off >>= 1)
        mx = fmaxf(mx, __shfl_xor_sync(0xffffffffu, mx, off));
    if ((tid & 31) == 0) red[tid >> 5] = mx;
    __syncthreads();
    mx = fmaxf(fmaxf(red[0], red[1]), fmaxf(red[2], red[3]));

    float sum = 0.f;
    for (int s = start + tid; s < end; s += 128)
        if (__ldg(&mk[s]) == 1) sum += expf(sc[s] - mx);
    __shared__ float red2[4];
#pragma unroll
    for (int off = 16; off > 0; off >>= 1)
        sum += __shfl_xor_sync(0xffffffffu, sum, off);
    if ((tid & 31) == 0) red2[tid >> 5] = sum;
    __syncthreads();
    if (tid == 0) {
        g_mx[bk] = mx;
        g_denom[bk] = red2[0] + red2[1] + red2[2] + red2[3];
    }
}

// ======================================================================
// K3: block_embed[b,k,:] = sum_s w[s] * h[b,s,:]   (segmented)
// one block per (b,k); 256 threads, float4 per thread over H=1024
// ======================================================================
__global__ __launch_bounds__(256)
void k3_block_embed(const float* __restrict__ h,
                    const int* __restrict__ mask,
                    const int* __restrict__ bnd) {
    const int bk = blockIdx.x;
    const int b = bk >> 6, k = bk & 63;
    int start = __ldg(&bnd[b * Kz + k]);
    int end = (k == Kz - 1) ? Sz : __ldg(&bnd[b * Kz + k + 1]);
    start = max(0, min(start, Sz));
    end = max(start, min(end, Sz));
    const float mx = g_mx[bk];
    const float den = g_denom[bk];
    const float inv = (den > 0.f) ? 1.f / fmaxf(den, 1e-30f) : 0.f;
    const int tid = threadIdx.x;

    const float* sc = g_tok_scores + b * Sz;
    const int* mk = mask + b * Sz;
    const float* hb = h + (size_t)b * Sz * Hz;

    __shared__ float wts[128];
    float4 acc = make_float4(0.f, 0.f, 0.f, 0.f);

    for (int cs = start; cs < end; cs += 128) {
        const int n = min(128, end - cs);
        if (tid < 128) {
            int s = cs + tid;
            float w = 0.f;
            if (s < end && __ldg(&mk[s]) == 1) w = expf(sc[s] - mx) * inv;
            wts[tid] = w;
        }
        __syncthreads();
        for (int i = 0; i < n; i++) {
            float w = wts[i];
            if (w != 0.f) {
                float4 hv = *(const float4*)(hb + (size_t)(cs + i) * Hz + tid * 4);
                acc.x = fmaf(w, hv.x, acc.x);
                acc.y = fmaf(w, hv.y, acc.y);
                acc.z = fmaf(w, hv.z, acc.z);
                acc.w = fmaf(w, hv.w, acc.w);
            }
        }
        __syncthreads();
    }
    *(float4*)(g_be + (size_t)bk * Hz + tid * 4) = acc;
}

// ======================================================================
// K4a: split-K partial GEMM for blk pre-activations.
// grid = 128 row-groups (4 bk rows each) x 4 d-chunks (256 d each).
// thread j owns column j; 4 be rows staged in smem; w1 streamed coalesced.
// ======================================================================
__global__ __launch_bounds__(256)
void k4a_blk_partial(const float* __restrict__ w1) {
    const int group = blockIdx.x >> 2;       // 0..127
    const int chunk = blockIdx.x & 3;        // 0..3
    const int bk0 = group * 4;
    const int d0 = chunk * K4_DCH;
    const int j = threadIdx.x;

    __shared__ float bes[4][K4_DCH];         // 4 KB
#pragma unroll
    for (int r = 0; r < 4; r++)
        bes[r][j] = g_be[(size_t)(bk0 + r) * Hz + d0 + j];
    __syncthreads();

    float a0 = 0.f, a1 = 0.f, a2 = 0.f, a3 = 0.f;
    const float* w1c = w1 + (size_t)d0 * HQ + j;
#pragma unroll 8
    for (int dd = 0; dd < K4_DCH; dd++) {
        float w = __ldg(w1c + (size_t)dd * HQ);
        a0 = fmaf(bes[0][dd], w, a0);
        a1 = fmaf(bes[1][dd], w, a1);
        a2 = fmaf(bes[2][dd], w, a2);
        a3 = fmaf(bes[3][dd], w, a3);
    }
    float* p = g_part + (size_t)chunk * (Bz * Kz * HQ) + (size_t)bk0 * HQ + j;
    p[0 * HQ] = a0;
    p[1 * HQ] = a1;
    p[2 * HQ] = a2;
    p[3 * HQ] = a3;
}

// ======================================================================
// K4b: combine partials -> tanh -> w2 dot -> blk score (+ validity)
// grid 128 (4 bk rows per block), 256 threads (thread = column j)
// ======================================================================
__global__ __launch_bounds__(256)
void k4b_blk_scores(const float* __restrict__ b1,
                    const float* __restrict__ w2,
                    const float* __restrict__ b2) {
    const int bk0 = blockIdx.x * 4;
    const int j = threadIdx.x;
    const float b1j = b1[j], w2j = w2[j];

    float v[4];
#pragma unroll
    for (int r = 0; r < 4; r++) {
        float a = 0.f;
#pragma unroll
        for (int c = 0; c < K4_CHUNKS; c++)
            a += g_part[(size_t)c * (Bz * Kz * HQ) + (size_t)(bk0 + r) * HQ + j];
        v[r] = tanhf(a + b1j) * w2j;
    }

    __shared__ float red[4][8];
    const int lane = j & 31, wid = j >> 5;
#pragma unroll
    for (int r = 0; r < 4; r++) {
        float x = v[r];
#pragma unroll
        for (int off = 16; off > 0; off >>= 1)
            x += __shfl_xor_sync(0xffffffffu, x, off);
        if (lane == 0) red[r][wid] = x;
    }
    __syncthreads();
    if (j < 4) {
        float s = 0.f;
#pragma unroll
        for (int w = 0; w < 8; w++) s += red[j][w];
        s += b2[0];
        int bk = bk0 + j;
        g_blk_score[bk] = (g_denom[bk] > 0.f) ? s : NEGV;
    }
}

// ======================================================================
// K5: per batch: softmax over blocks -> func -> out proj -> L2 normalize
// one block per b, 256 threads (thread = output channel e)
// ======================================================================
__global__ __launch_bounds__(256)
void k5_out(const float* __restrict__ out_w,
            const float* __restrict__ out_b,
            float* __restrict__ out) {
    const int b = blockIdx.x;
    const int tid = threadIdx.x;
    __shared__ float bw[Kz];
    __shared__ float func[Hz];
    __shared__ float red[8];

    if (tid == 0) {
        float mx = NEGV;
        for (int k = 0; k < Kz; k++) mx = fmaxf(mx, g_blk_score[b * Kz + k]);
        float s = 0.f;
        for (int k = 0; k < Kz; k++) {
            float e = expf(g_blk_score[b * Kz + k] - mx);
            bw[k] = e;
            s += e;
        }
        float inv = 1.f / s;
        for (int k = 0; k < Kz; k++) bw[k] *= inv;
    }
    __syncthreads();

    // func[d] = sum_k bw[k] * be[b,k,d]
    const float* be = g_be + (size_t)b * Kz * Hz;
    float4 acc = make_float4(0.f, 0.f, 0.f, 0.f);
    for (int k = 0; k < Kz; k++) {
        float w = bw[k];
        float4 v = *(const float4*)(be + (size_t)k * Hz + tid * 4);
        acc.x = fmaf(w, v.x, acc.x);
        acc.y = fmaf(w, v.y, acc.y);
        acc.z = fmaf(w, v.z, acc.z);
        acc.w = fmaf(w, v.w, acc.w);
    }
    *(float4*)&func[tid * 4] = acc;
    __syncthreads();

    // out[e] = func @ out_w[:,e] + out_b[e]
    float o = out_b[tid];
    for (int d = 0; d < Hz; d++)
        o = fmaf(func[d], out_w[(size_t)d * Ez + tid], o);

    // L2 norm across the 256 outputs
    float ss = o * o;
    const int lane = tid & 31, wid = tid >> 5;
#pragma unroll
    for (int off = 16; off > 0; off >>= 1)
        ss += __shfl_xor_sync(0xffffffffu, ss, off);
    if (lane == 0) red[wid] = ss;
    __syncthreads();
    float tot = 0.f;
#pragma unroll
    for (int w = 0; w < 8; w++) tot += red[w];
    float nrm = fmaxf(sqrtf(tot), 1e-12f);
    out[b * Ez + tid] = o / nrm;
}

// ======================================================================
extern "C" void kernel_launch(void* const* d_in, const int* in_sizes, int n_in,
                              void* d_out, int out_size) {
    const float* hidden = (const float*)d_in[0];
    const int* mask = (const int*)d_in[1];
    const int* bnd = (const int*)d_in[2];
    const float* tok_w1 = (const float*)d_in[3];
    const float* tok_b1 = (const float*)d_in[4];
    const float* tok_w2 = (const float*)d_in[5];
    const float* tok_b2 = (const float*)d_in[6];
    const float* blk_w1 = (const float*)d_in[7];
    const float* blk_b1 = (const float*)d_in[8];
    const float* blk_w2 = (const float*)d_in[9];
    const float* blk_b2 = (const float*)d_in[10];
    const float* out_w = (const float*)d_in[11];
    const float* out_b = (const float*)d_in[12];
    float* out = (float*)d_out;

    k1_tok_scores<<<(Bz * Sz) / 64, 256>>>(hidden, tok_w1, tok_b1, tok_w2, tok_b2);
    k2_seg_stats<<<Bz * Kz, 128>>>(mask, bnd);
    k3_block_embed<<<Bz * Kz, 256>>>(hidden, mask, bnd);
    k4a_blk_partial<<<(Bz * Kz / 4) * K4_CHUNKS, 256>>>(blk_w1);
    k4b_blk_scores<<<Bz * Kz / 4, 256>>>(blk_b1, blk_w2, blk_b2);
    k5_out<<<Bz, 256>>>(out_w, out_b, out);
}

// round 7
// speedup vs baseline: 2.2908x; 2.0626x over previous
#include <cuda_runtime.h>
#include <math.h>
#include <stdint.h>

#define Bz 8
#define Sz 4096
#define Hz 1024
#define Ez 256
#define Kz 64
#define HQ 256
#define NEGV (-1e30f)
#define K4_CHUNKS 8
#define K4_DCH (Hz / K4_CHUNKS)   // 128

// ---------------- scratch (static __device__, no allocs) ----------------
__device__ float g_tok_scores[Bz * Sz];        // [B,S]
__device__ float g_mx[Bz * Kz];                // per-(b,k) max
__device__ float g_denom[Bz * Kz];             // per-(b,k) sum of exp
__device__ float g_be[(size_t)Bz * Kz * Hz];   // block_embed [B,K,H] (2 MB)
__device__ float g_blk_score[Bz * Kz];         // stage-2 scores
__device__ float g_part[(size_t)K4_CHUNKS * Bz * Kz * HQ];  // k4 split-K partials (4 MB)

__device__ __forceinline__ uint32_t f2tf32(float x) {
    uint32_t u;
    asm("cvt.rna.tf32.f32 %0, %1;" : "=r"(u) : "f"(x));
    return u;
}

__device__ __forceinline__ void mma_tf32(float* d, const uint32_t* a, const uint32_t* b) {
    asm volatile(
        "mma.sync.aligned.m16n8k8.row.col.f32.tf32.tf32.f32 "
        "{%0,%1,%2,%3},{%4,%5,%6,%7},{%8,%9},{%0,%1,%2,%3};\n"
        : "+f"(d[0]), "+f"(d[1]), "+f"(d[2]), "+f"(d[3])
        : "r"(a[0]), "r"(a[1]), "r"(a[2]), "r"(a[3]), "r"(b[0]), "r"(b[1]));
}

// ======================================================================
// K1: tok_scores = tanh(h @ tok_w1 + b1) @ tok_w2 + b2   (tf32 MMA)
// BM=64, BN=256(full Hq), BK=32; 256 thr, 8 warps in 2x4 (M x N) grid;
// warp tile 32x64 via m16n8k8. Epilogue fuses tanh + w2-dot + row reduce.
// ======================================================================
__global__ __launch_bounds__(256, 2)
void k1_tok_scores(const float* __restrict__ h,
                   const float* __restrict__ w1,
                   const float* __restrict__ b1,
                   const float* __restrict__ w2,
                   const float* __restrict__ b2) {
    __shared__ uint32_t As[64][36];     // tf32 bits, bank map 4*row+k distinct
    __shared__ uint32_t Bs[32][264];    // tf32 bits, bank map 8*k+n distinct
    __shared__ float rowsum[64];

    const int tid = threadIdx.x;
    const int rowbase = blockIdx.x * 64;
    const int wid = tid >> 5;
    const int lane = tid & 31;
    const int warpM = wid >> 2;         // 0..1
    const int warpN = wid & 3;          // 0..3
    const int g = lane >> 2;            // group id 0..7
    const int c = lane & 3;             // thread-in-group 0..3
    const int nb = warpN * 64;

    if (tid < 64) rowsum[tid] = 0.f;

    float acc[2][8][4];
#pragma unroll
    for (int mt = 0; mt < 2; mt++)
#pragma unroll
        for (int nt = 0; nt < 8; nt++)
#pragma unroll
            for (int r = 0; r < 4; r++) acc[mt][nt][r] = 0.f;

    for (int k0 = 0; k0 < Hz; k0 += 32) {
        __syncthreads();
        // A tile: 64 rows x 32 k, cvt to tf32
#pragma unroll
        for (int e = 0; e < 2; e++) {
            int f = tid + e * 256;          // 0..511 float4 slots
            int row = f >> 3;               // 0..63
            int c4 = (f & 7) * 4;           // 0..28
            float4 v = *(const float4*)(h + (size_t)(rowbase + row) * Hz + k0 + c4);
            As[row][c4 + 0] = f2tf32(v.x);
            As[row][c4 + 1] = f2tf32(v.y);
            As[row][c4 + 2] = f2tf32(v.z);
            As[row][c4 + 3] = f2tf32(v.w);
        }
        // B tile: 32 k x 256 n
#pragma unroll
        for (int e = 0; e < 8; e++) {
            int f = tid + e * 256;          // 0..2047 float4 slots
            int row = f >> 6;               // 0..31
            int c4 = (f & 63) * 4;          // 0..252
            float4 v = *(const float4*)(w1 + (size_t)(k0 + row) * HQ + c4);
            Bs[row][c4 + 0] = f2tf32(v.x);
            Bs[row][c4 + 1] = f2tf32(v.y);
            Bs[row][c4 + 2] = f2tf32(v.z);
            Bs[row][c4 + 3] = f2tf32(v.w);
        }
        __syncthreads();

#pragma unroll
        for (int ks = 0; ks < 4; ks++) {
            const int kk = ks * 8;
            uint32_t a[2][4], b[8][2];
#pragma unroll
            for (int mt = 0; mt < 2; mt++) {
                const int mb = warpM * 32 + mt * 16;
                a[mt][0] = As[mb + g][kk + c];
                a[mt][1] = As[mb + g + 8][kk + c];
                a[mt][2] = As[mb + g][kk + c + 4];
                a[mt][3] = As[mb + g + 8][kk + c + 4];
            }
#pragma unroll
            for (int nt = 0; nt < 8; nt++) {
                const int n = nb + nt * 8 + g;
                b[nt][0] = Bs[kk + c][n];
                b[nt][1] = Bs[kk + c + 4][n];
            }
#pragma unroll
            for (int mt = 0; mt < 2; mt++)
#pragma unroll
                for (int nt = 0; nt < 8; nt++)
                    mma_tf32(acc[mt][nt], a[mt], b[nt]);
        }
    }

    // epilogue: row score = sum_col tanh(acc + b1[col]) * w2[col]
#pragma unroll
    for (int mt = 0; mt < 2; mt++) {
#pragma unroll
        for (int half = 0; half < 2; half++) {
            float p = 0.f;
#pragma unroll
            for (int nt = 0; nt < 8; nt++) {
                const int col0 = nb + nt * 8 + c * 2;
                const float v0 = acc[mt][nt][half * 2 + 0] + __ldg(&b1[col0]);
                const float v1 = acc[mt][nt][half * 2 + 1] + __ldg(&b1[col0 + 1]);
                p += tanhf(v0) * __ldg(&w2[col0]) + tanhf(v1) * __ldg(&w2[col0 + 1]);
            }
            p += __shfl_xor_sync(0xffffffffu, p, 1);
            p += __shfl_xor_sync(0xffffffffu, p, 2);
            if (c == 0)
                atomicAdd(&rowsum[warpM * 32 + mt * 16 + half * 8 + g], p);
        }
    }
    __syncthreads();
    if (tid < 64)
        g_tok_scores[rowbase + tid] = rowsum[tid] + b2[0];
}

// ======================================================================
// K2: per-(b,k) segment max & sum-of-exp over contiguous token range
// ======================================================================
__global__ __launch_bounds__(128)
void k2_seg_stats(const int* __restrict__ mask, const int* __restrict__ bnd) {
    const int bk = blockIdx.x;
    const int b = bk >> 6, k = bk & 63;
    int start = __ldg(&bnd[b * Kz + k]);
    int end = (k == Kz - 1) ? Sz : __ldg(&bnd[b * Kz + k + 1]);
    start = max(0, min(start, Sz));
    end = max(start, min(end, Sz));
    const float* sc = g_tok_scores + b * Sz;
    const int* mk = mask + b * Sz;
    const int tid = threadIdx.x;

    float mx = NEGV;
    for (int s = start + tid; s < end; s += 128)
        if (__ldg(&mk[s]) == 1) mx = fmaxf(mx, sc[s]);
    __shared__ float red[4];
#pragma unroll
    for (int off = 16; off > 0; off >>= 1)
        mx = fmaxf(mx, __shfl_xor_sync(0xffffffffu, mx, off));
    if ((tid & 31) == 0) red[tid >> 5] = mx;
    __syncthreads();
    mx = fmaxf(fmaxf(red[0], red[1]), fmaxf(red[2], red[3]));

    float sum = 0.f;
    for (int s = start + tid; s < end; s += 128)
        if (__ldg(&mk[s]) == 1) sum += expf(sc[s] - mx);
    __shared__ float red2[4];
#pragma unroll
    for (int off = 16; off > 0; off >>= 1)
        sum += __shfl_xor_sync(0xffffffffu, sum, off);
    if ((tid & 31) == 0) red2[tid >> 5] = sum;
    __syncthreads();
    if (tid == 0) {
        g_mx[bk] = mx;
        g_denom[bk] = red2[0] + red2[1] + red2[2] + red2[3];
    }
}

// ======================================================================
// K3: block_embed[b,k,:] = sum_s w[s] * h[b,s,:]   (segmented)
// ======================================================================
__global__ __launch_bounds__(256)
void k3_block_embed(const float* __restrict__ h,
                    const int* __restrict__ mask,
                    const int* __restrict__ bnd) {
    const int bk = blockIdx.x;
    const int b = bk >> 6, k = bk & 63;
    int start = __ldg(&bnd[b * Kz + k]);
    int end = (k == Kz - 1) ? Sz : __ldg(&bnd[b * Kz + k + 1]);
    start = max(0, min(start, Sz));
    end = max(start, min(end, Sz));
    const float mx = g_mx[bk];
    const float den = g_denom[bk];
    const float inv = (den > 0.f) ? 1.f / fmaxf(den, 1e-30f) : 0.f;
    const int tid = threadIdx.x;

    const float* sc = g_tok_scores + b * Sz;
    const int* mk = mask + b * Sz;
    const float* hb = h + (size_t)b * Sz * Hz;

    __shared__ float wts[128];
    float4 acc = make_float4(0.f, 0.f, 0.f, 0.f);

    for (int cs = start; cs < end; cs += 128) {
        const int n = min(128, end - cs);
        if (tid < 128) {
            int s = cs + tid;
            float w = 0.f;
            if (s < end && __ldg(&mk[s]) == 1) w = expf(sc[s] - mx) * inv;
            wts[tid] = w;
        }
        __syncthreads();
        for (int i = 0; i < n; i++) {
            float w = wts[i];
            if (w != 0.f) {
                float4 hv = *(const float4*)(hb + (size_t)(cs + i) * Hz + tid * 4);
                acc.x = fmaf(w, hv.x, acc.x);
                acc.y = fmaf(w, hv.y, acc.y);
                acc.z = fmaf(w, hv.z, acc.z);
                acc.w = fmaf(w, hv.w, acc.w);
            }
        }
        __syncthreads();
    }
    *(float4*)(g_be + (size_t)bk * Hz + tid * 4) = acc;
}

// ======================================================================
// K4a: split-K partial GEMM for blk pre-activations.
// grid = 128 row-groups (4 bk rows) x 8 d-chunks (128 d each).
// ======================================================================
__global__ __launch_bounds__(256)
void k4a_blk_partial(const float* __restrict__ w1) {
    const int group = blockIdx.x >> 3;       // 0..127
    const int chunk = blockIdx.x & 7;        // 0..7
    const int bk0 = group * 4;
    const int d0 = chunk * K4_DCH;
    const int j = threadIdx.x;

    __shared__ float bes[4][K4_DCH];         // 2 KB
#pragma unroll
    for (int e = 0; e < 2; e++) {
        int idx = j + e * 256;               // 0..511
        int r = idx >> 7, d = idx & 127;
        bes[r][d] = g_be[(size_t)(bk0 + r) * Hz + d0 + d];
    }
    __syncthreads();

    float a0 = 0.f, a1 = 0.f, a2 = 0.f, a3 = 0.f;
    const float* w1c = w1 + (size_t)d0 * HQ + j;
#pragma unroll 8
    for (int dd = 0; dd < K4_DCH; dd++) {
        float w = __ldg(w1c + (size_t)dd * HQ);
        a0 = fmaf(bes[0][dd], w, a0);
        a1 = fmaf(bes[1][dd], w, a1);
        a2 = fmaf(bes[2][dd], w, a2);
        a3 = fmaf(bes[3][dd], w, a3);
    }
    float* p = g_part + (size_t)chunk * (Bz * Kz * HQ) + (size_t)bk0 * HQ + j;
    p[0 * HQ] = a0;
    p[1 * HQ] = a1;
    p[2 * HQ] = a2;
    p[3 * HQ] = a3;
}

// ======================================================================
// K4b: combine partials -> tanh -> w2 dot -> blk score (+ validity)
// ======================================================================
__global__ __launch_bounds__(256)
void k4b_blk_scores(const float* __restrict__ b1,
                    const float* __restrict__ w2,
                    const float* __restrict__ b2) {
    const int bk0 = blockIdx.x * 4;
    const int j = threadIdx.x;
    const float b1j = b1[j], w2j = w2[j];

    float v[4];
#pragma unroll
    for (int r = 0; r < 4; r++) {
        float a = 0.f;
#pragma unroll
        for (int c = 0; c < K4_CHUNKS; c++)
            a += g_part[(size_t)c * (Bz * Kz * HQ) + (size_t)(bk0 + r) * HQ + j];
        v[r] = tanhf(a + b1j) * w2j;
    }

    __shared__ float red[4][8];
    const int lane = j & 31, wid = j >> 5;
#pragma unroll
    for (int r = 0; r < 4; r++) {
        float x = v[r];
#pragma unroll
        for (int off = 16; off > 0; off >>= 1)
            x += __shfl_xor_sync(0xffffffffu, x, off);
        if (lane == 0) red[r][wid] = x;
    }
    __syncthreads();
    if (j < 4) {
        float s = 0.f;
#pragma unroll
        for (int w = 0; w < 8; w++) s += red[j][w];
        s += b2[0];
        int bk = bk0 + j;
        g_blk_score[bk] = (g_denom[bk] > 0.f) ? s : NEGV;
    }
}

// ======================================================================
// K5: per batch: softmax over blocks -> func -> out proj -> L2 normalize
// ======================================================================
__global__ __launch_bounds__(256)
void k5_out(const float* __restrict__ out_w,
            const float* __restrict__ out_b,
            float* __restrict__ out) {
    const int b = blockIdx.x;
    const int tid = threadIdx.x;
    __shared__ float bw[Kz];
    __shared__ float func[Hz];
    __shared__ float red[8];

    if (tid == 0) {
        float mx = NEGV;
        for (int k = 0; k < Kz; k++) mx = fmaxf(mx, g_blk_score[b * Kz + k]);
        float s = 0.f;
        for (int k = 0; k < Kz; k++) {
            float e = expf(g_blk_score[b * Kz + k] - mx);
            bw[k] = e;
            s += e;
        }
        float inv = 1.f / s;
        for (int k = 0; k < Kz; k++) bw[k] *= inv;
    }
    __syncthreads();

    const float* be = g_be + (size_t)b * Kz * Hz;
    float4 acc = make_float4(0.f, 0.f, 0.f, 0.f);
    for (int k = 0; k < Kz; k++) {
        float w = bw[k];
        float4 v = *(const float4*)(be + (size_t)k * Hz + tid * 4);
        acc.x = fmaf(w, v.x, acc.x);
        acc.y = fmaf(w, v.y, acc.y);
        acc.z = fmaf(w, v.z, acc.z);
        acc.w = fmaf(w, v.w, acc.w);
    }
    *(float4*)&func[tid * 4] = acc;
    __syncthreads();

    float o = out_b[tid];
    for (int d = 0; d < Hz; d++)
        o = fmaf(func[d], out_w[(size_t)d * Ez + tid], o);

    float ss = o * o;
    const int lane = tid & 31, wid = tid >> 5;
#pragma unroll
    for (int off = 16; off > 0; off >>= 1)
        ss += __shfl_xor_sync(0xffffffffu, ss, off);
    if (lane == 0) red[wid] = ss;
    __syncthreads();
    float tot = 0.f;
#pragma unroll
    for (int w = 0; w < 8; w++) tot += red[w];
    float nrm = fmaxf(sqrtf(tot), 1e-12f);
    out[b * Ez + tid] = o / nrm;
}

// ======================================================================
extern "C" void kernel_launch(void* const* d_in, const int* in_sizes, int n_in,
                              void* d_out, int out_size) {
    const float* hidden = (const float*)d_in[0];
    const int* mask = (const int*)d_in[1];
    const int* bnd = (const int*)d_in[2];
    const float* tok_w1 = (const float*)d_in[3];
    const float* tok_b1 = (const float*)d_in[4];
    const float* tok_w2 = (const float*)d_in[5];
    const float* tok_b2 = (const float*)d_in[6];
    const float* blk_w1 = (const float*)d_in[7];
    const float* blk_b1 = (const float*)d_in[8];
    const float* blk_w2 = (const float*)d_in[9];
    const float* blk_b2 = (const float*)d_in[10];
    const float* out_w = (const float*)d_in[11];
    const float* out_b = (const float*)d_in[12];
    float* out = (float*)d_out;

    k1_tok_scores<<<(Bz * Sz) / 64, 256>>>(hidden, tok_w1, tok_b1, tok_w2, tok_b2);
    k2_seg_stats<<<Bz * Kz, 128>>>(mask, bnd);
    k3_block_embed<<<Bz * Kz, 256>>>(hidden, mask, bnd);
    k4a_blk_partial<<<(Bz * Kz / 4) * K4_CHUNKS, 256>>>(blk_w1);
    k4b_blk_scores<<<Bz * Kz / 4, 256>>>(blk_b1, blk_w2, blk_b2);
    k5_out<<<Bz, 256>>>(out_w, out_b, out);
}

// round 11
// speedup vs baseline: 2.5153x; 1.0980x over previous
#include <cuda_runtime.h>
#include <math.h>
#include <stdint.h>

#define Bz 8
#define Sz 4096
#define Hz 1024
#define Ez 256
#define Kz 64
#define HQ 256
#define NEGV (-1e30f)
#define K4_CHUNKS 8
#define K4_DCH (Hz / K4_CHUNKS)   // 128

// k1 tile geometry
#define K1_BM 128
#define K1_BK 32
#define K1_APAD 36    // (4g+c) bank-distinct
#define K1_BPAD 264   // (8c+g) bank-distinct
#define K1_AW (K1_BM * K1_APAD)          // words per A buffer
#define K1_BW (K1_BK * K1_BPAD)          // words per B buffer
#define K1_SMEM_BYTES ((2 * K1_AW + 2 * K1_BW) * 4)   // 104448

// ---------------- scratch (static __device__, no allocs) ----------------
__device__ float g_tok_scores[Bz * Sz];        // [B,S]
__device__ float g_mx[Bz * Kz];                // per-(b,k) max
__device__ float g_denom[Bz * Kz];             // per-(b,k) sum of exp
__device__ float g_be[(size_t)Bz * Kz * Hz];   // block_embed [B,K,H] (2 MB)
__device__ float g_blk_score[Bz * Kz];         // stage-2 scores
__device__ float g_part[(size_t)K4_CHUNKS * Bz * Kz * HQ];  // k4 split-K partials (4 MB)

__device__ __forceinline__ void cp16(uint32_t dst_smem, const void* src) {
    asm volatile("cp.async.ca.shared.global [%0], [%1], 16;" :: "r"(dst_smem), "l"(src));
}

__device__ __forceinline__ void mma_tf32(float* d, const uint32_t* a, const uint32_t* b) {
    asm volatile(
        "mma.sync.aligned.m16n8k8.row.col.f32.tf32.tf32.f32 "
        "{%0,%1,%2,%3},{%4,%5,%6,%7},{%8,%9},{%0,%1,%2,%3};\n"
        : "+f"(d[0]), "+f"(d[1]), "+f"(d[2]), "+f"(d[3])
        : "r"(a[0]), "r"(a[1]), "r"(a[2]), "r"(a[3]), "r"(b[0]), "r"(b[1]));
}

// ======================================================================
// K1: tok_scores = tanh(h @ tok_w1 + b1) @ tok_w2 + b2   (tf32 MMA)
// BM=128, BN=256(full Hq), BK=32; 512 thr, 16 warps 4x4; warp tile 32x64.
// Double-buffered cp.async tiles (raw fp32 bits fed to tf32 mma).
// Epilogue fuses tanh + w2-dot + row reduction.
// ======================================================================
__global__ __launch_bounds__(512, 1)
void k1_tok_scores(const float* __restrict__ h,
                   const float* __restrict__ w1,
                   const float* __restrict__ b1,
                   const float* __restrict__ w2,
                   const float* __restrict__ b2) {
    extern __shared__ uint32_t dyn[];
    uint32_t* AsBase = dyn;                  // [2][128][36]
    uint32_t* BsBase = dyn + 2 * K1_AW;      // [2][32][264]
    __shared__ float rowsum[K1_BM];

    const int tid = threadIdx.x;
    const int rowbase = blockIdx.x * K1_BM;
    const int wid = tid >> 5;
    const int lane = tid & 31;
    const int warpM = wid >> 2;         // 0..3
    const int warpN = wid & 3;          // 0..3
    const int g = lane >> 2;            // 0..7
    const int c = lane & 3;             // 0..3
    const int nb = warpN * 64;

    const uint32_t as_sa = (uint32_t)__cvta_generic_to_shared(AsBase);
    const uint32_t bs_sa = (uint32_t)__cvta_generic_to_shared(BsBase);

    if (tid < K1_BM) rowsum[tid] = 0.f;

    float acc[2][8][4];
#pragma unroll
    for (int mt = 0; mt < 2; mt++)
#pragma unroll
        for (int nt = 0; nt < 8; nt++)
#pragma unroll
            for (int r = 0; r < 4; r++) acc[mt][nt][r] = 0.f;

    // A chunk map: f = tid + e*512 -> row=f>>3 (0..127), c4=(f&7)*4
    const int a_row = tid >> 3;
    const int a_c4 = (tid & 7) * 4;
    // B chunk map: f = tid + e*512 -> row=f>>6, c4=(f&63)*4
    const int b_row = tid >> 6;               // 0..7
    const int b_c4 = (tid & 63) * 4;

#define ISSUE_TILES(K0, BUF)                                                     \
    do {                                                                         \
        cp16(as_sa + (((BUF) * K1_BM + a_row) * K1_APAD + a_c4) * 4,             \
             h + (size_t)(rowbase + a_row) * Hz + (K0) + a_c4);                  \
        cp16(as_sa + (((BUF) * K1_BM + a_row + 64) * K1_APAD + a_c4) * 4,        \
             h + (size_t)(rowbase + a_row + 64) * Hz + (K0) + a_c4);             \
        cp16(bs_sa + (((BUF) * K1_BK + b_row) * K1_BPAD + b_c4) * 4,             \
             w1 + (size_t)((K0) + b_row) * HQ + b_c4);                           \
        cp16(bs_sa + (((BUF) * K1_BK + b_row + 8) * K1_BPAD + b_c4) * 4,         \
             w1 + (size_t)((K0) + b_row + 8) * HQ + b_c4);                       \
        cp16(bs_sa + (((BUF) * K1_BK + b_row + 16) * K1_BPAD + b_c4) * 4,        \
             w1 + (size_t)((K0) + b_row + 16) * HQ + b_c4);                      \
        cp16(bs_sa + (((BUF) * K1_BK + b_row + 24) * K1_BPAD + b_c4) * 4,        \
             w1 + (size_t)((K0) + b_row + 24) * HQ + b_c4);                      \
        asm volatile("cp.async.commit_group;");                                  \
    } while (0)

    ISSUE_TILES(0, 0);

    for (int it = 0; it < Hz / K1_BK; it++) {
        const int cur = it & 1;
        if (it < Hz / K1_BK - 1) {
            ISSUE_TILES((it + 1) * K1_BK, cur ^ 1);
            asm volatile("cp.async.wait_group 1;");
        } else {
            asm volatile("cp.async.wait_group 0;");
        }
        __syncthreads();

        const uint32_t* As = AsBase + cur * K1_AW;
        const uint32_t* Bs = BsBase + cur * K1_BW;
#pragma unroll
        for (int ks = 0; ks < 4; ks++) {
            const int kk = ks * 8;
            uint32_t a[2][4], b[8][2];
#pragma unroll
            for (int mt = 0; mt < 2; mt++) {
                const int mb = warpM * 32 + mt * 16;
                a[mt][0] = As[(mb + g) * K1_APAD + kk + c];
                a[mt][1] = As[(mb + g + 8) * K1_APAD + kk + c];
                a[mt][2] = As[(mb + g) * K1_APAD + kk + c + 4];
                a[mt][3] = As[(mb + g + 8) * K1_APAD + kk + c + 4];
            }
#pragma unroll
            for (int nt = 0; nt < 8; nt++) {
                const int n = nb + nt * 8 + g;
                b[nt][0] = Bs[(kk + c) * K1_BPAD + n];
                b[nt][1] = Bs[(kk + c + 4) * K1_BPAD + n];
            }
#pragma unroll
            for (int mt = 0; mt < 2; mt++)
#pragma unroll
                for (int nt = 0; nt < 8; nt++)
                    mma_tf32(acc[mt][nt], a[mt], b[nt]);
        }
        __syncthreads();   // all reads of 'cur' done before it is refilled
    }

    // epilogue: row score = sum_col tanh(acc + b1[col]) * w2[col]
#pragma unroll
    for (int mt = 0; mt < 2; mt++) {
#pragma unroll
        for (int half = 0; half < 2; half++) {
            float p = 0.f;
#pragma unroll
            for (int nt = 0; nt < 8; nt++) {
                const int col0 = nb + nt * 8 + c * 2;
                const float v0 = acc[mt][nt][half * 2 + 0] + __ldg(&b1[col0]);
                const float v1 = acc[mt][nt][half * 2 + 1] + __ldg(&b1[col0 + 1]);
                p += tanhf(v0) * __ldg(&w2[col0]) + tanhf(v1) * __ldg(&w2[col0 + 1]);
            }
            p += __shfl_xor_sync(0xffffffffu, p, 1);
            p += __shfl_xor_sync(0xffffffffu, p, 2);
            if (c == 0)
                atomicAdd(&rowsum[warpM * 32 + mt * 16 + half * 8 + g], p);
        }
    }
    __syncthreads();
    if (tid < K1_BM)
        g_tok_scores[rowbase + tid] = rowsum[tid] + b2[0];
}

// ======================================================================
// K2: per-(b,k) segment max & sum-of-exp over contiguous token range
// ======================================================================
__global__ __launch_bounds__(128)
void k2_seg_stats(const int* __restrict__ mask, const int* __restrict__ bnd) {
    const int bk = blockIdx.x;
    const int b = bk >> 6, k = bk & 63;
    int start = __ldg(&bnd[b * Kz + k]);
    int end = (k == Kz - 1) ? Sz : __ldg(&bnd[b * Kz + k + 1]);
    start = max(0, min(start, Sz));
    end = max(start, min(end, Sz));
    const float* sc = g_tok_scores + b * Sz;
    const int* mk = mask + b * Sz;
    const int tid = threadIdx.x;

    float mx = NEGV;
    for (int s = start + tid; s < end; s += 128)
        if (__ldg(&mk[s]) == 1) mx = fmaxf(mx, sc[s]);
    __shared__ float red[4];
#pragma unroll
    for (int off = 16; off > 0; off >>= 1)
        mx = fmaxf(mx, __shfl_xor_sync(0xffffffffu, mx, off));
    if ((tid & 31) == 0) red[tid >> 5] = mx;
    __syncthreads();
    mx = fmaxf(fmaxf(red[0], red[1]), fmaxf(red[2], red[3]));

    float sum = 0.f;
    for (int s = start + tid; s < end; s += 128)
        if (__ldg(&mk[s]) == 1) sum += expf(sc[s] - mx);
    __shared__ float red2[4];
#pragma unroll
    for (int off = 16; off > 0; off >>= 1)
        sum += __shfl_xor_sync(0xffffffffu, sum, off);
    if ((tid & 31) == 0) red2[tid >> 5] = sum;
    __syncthreads();
    if (tid == 0) {
        g_mx[bk] = mx;
        g_denom[bk] = red2[0] + red2[1] + red2[2] + red2[3];
    }
}

// ======================================================================
// K3: block_embed[b,k,:] = sum_s w[s] * h[b,s,:]   (segmented)
// ======================================================================
__global__ __launch_bounds__(256)
void k3_block_embed(const float* __restrict__ h,
                    const int* __restrict__ mask,
                    const int* __restrict__ bnd) {
    const int bk = blockIdx.x;
    const int b = bk >> 6, k = bk & 63;
    int start = __ldg(&bnd[b * Kz + k]);
    int end = (k == Kz - 1) ? Sz : __ldg(&bnd[b * Kz + k + 1]);
    start = max(0, min(start, Sz));
    end = max(start, min(end, Sz));
    const float mx = g_mx[bk];
    const float den = g_denom[bk];
    const float inv = (den > 0.f) ? 1.f / fmaxf(den, 1e-30f) : 0.f;
    const int tid = threadIdx.x;

    const float* sc = g_tok_scores + b * Sz;
    const int* mk = mask + b * Sz;
    const float* hb = h + (size_t)b * Sz * Hz;

    __shared__ float wts[128];
    float4 acc = make_float4(0.f, 0.f, 0.f, 0.f);

    for (int cs = start; cs < end; cs += 128) {
        const int n = min(128, end - cs);
        if (tid < 128) {
            int s = cs + tid;
            float w = 0.f;
            if (s < end && __ldg(&mk[s]) == 1) w = expf(sc[s] - mx) * inv;
            wts[tid] = w;
        }
        __syncthreads();
        for (int i = 0; i < n; i++) {
            float w = wts[i];
            if (w != 0.f) {
                float4 hv = *(const float4*)(hb + (size_t)(cs + i) * Hz + tid * 4);
                acc.x = fmaf(w, hv.x, acc.x);
                acc.y = fmaf(w, hv.y, acc.y);
                acc.z = fmaf(w, hv.z, acc.z);
                acc.w = fmaf(w, hv.w, acc.w);
            }
        }
        __syncthreads();
    }
    *(float4*)(g_be + (size_t)bk * Hz + tid * 4) = acc;
}

// ======================================================================
// K4a: split-K partial GEMM for blk pre-activations.
// grid = 128 row-groups (4 bk rows) x 8 d-chunks (128 d each).
// ======================================================================
__global__ __launch_bounds__(256)
void k4a_blk_partial(const float* __restrict__ w1) {
    const int group = blockIdx.x >> 3;       // 0..127
    const int chunk = blockIdx.x & 7;        // 0..7
    const int bk0 = group * 4;
    const int d0 = chunk * K4_DCH;
    const int j = threadIdx.x;

    __shared__ float bes[4][K4_DCH];         // 2 KB
#pragma unroll
    for (int e = 0; e < 2; e++) {
        int idx = j + e * 256;               // 0..511
        int r = idx >> 7, d = idx & 127;
        bes[r][d] = g_be[(size_t)(bk0 + r) * Hz + d0 + d];
    }
    __syncthreads();

    float a0 = 0.f, a1 = 0.f, a2 = 0.f, a3 = 0.f;
    const float* w1c = w1 + (size_t)d0 * HQ + j;
#pragma unroll 8
    for (int dd = 0; dd < K4_DCH; dd++) {
        float w = __ldg(w1c + (size_t)dd * HQ);
        a0 = fmaf(bes[0][dd], w, a0);
        a1 = fmaf(bes[1][dd], w, a1);
        a2 = fmaf(bes[2][dd], w, a2);
        a3 = fmaf(bes[3][dd], w, a3);
    }
    float* p = g_part + (size_t)chunk * (Bz * Kz * HQ) + (size_t)bk0 * HQ + j;
    p[0 * HQ] = a0;
    p[1 * HQ] = a1;
    p[2 * HQ] = a2;
    p[3 * HQ] = a3;
}

// ======================================================================
// K4b: combine partials -> tanh -> w2 dot -> blk score (+ validity)
// ======================================================================
__global__ __launch_bounds__(256)
void k4b_blk_scores(const float* __restrict__ b1,
                    const float* __restrict__ w2,
                    const float* __restrict__ b2) {
    const int bk0 = blockIdx.x * 4;
    const int j = threadIdx.x;
    const float b1j = b1[j], w2j = w2[j];

    float v[4];
#pragma unroll
    for (int r = 0; r < 4; r++) {
        float a = 0.f;
#pragma unroll
        for (int c = 0; c < K4_CHUNKS; c++)
            a += g_part[(size_t)c * (Bz * Kz * HQ) + (size_t)(bk0 + r) * HQ + j];
        v[r] = tanhf(a + b1j) * w2j;
    }

    __shared__ float red[4][8];
    const int lane = j & 31, wid = j >> 5;
#pragma unroll
    for (int r = 0; r < 4; r++) {
        float x = v[r];
#pragma unroll
        for (int off = 16; off > 0; off >>= 1)
            x += __shfl_xor_sync(0xffffffffu, x, off);
        if (lane == 0) red[r][wid] = x;
    }
    __syncthreads();
    if (j < 4) {
        float s = 0.f;
#pragma unroll
        for (int w = 0; w < 8; w++) s += red[j][w];
        s += b2[0];
        int bk = bk0 + j;
        g_blk_score[bk] = (g_denom[bk] > 0.f) ? s : NEGV;
    }
}

// ======================================================================
// K5: per batch: softmax over blocks -> func -> out proj -> L2 normalize
// ======================================================================
__global__ __launch_bounds__(256)
void k5_out(const float* __restrict__ out_w,
            const float* __restrict__ out_b,
            float* __restrict__ out) {
    const int b = blockIdx.x;
    const int tid = threadIdx.x;
    __shared__ float bw[Kz];
    __shared__ float func[Hz];
    __shared__ float red[8];

    if (tid == 0) {
        float mx = NEGV;
        for (int k = 0; k < Kz; k++) mx = fmaxf(mx, g_blk_score[b * Kz + k]);
        float s = 0.f;
        for (int k = 0; k < Kz; k++) {
            float e = expf(g_blk_score[b * Kz + k] - mx);
            bw[k] = e;
            s += e;
        }
        float inv = 1.f / s;
        for (int k = 0; k < Kz; k++) bw[k] *= inv;
    }
    __syncthreads();

    const float* be = g_be + (size_t)b * Kz * Hz;
    float4 acc = make_float4(0.f, 0.f, 0.f, 0.f);
    for (int k = 0; k < Kz; k++) {
        float w = bw[k];
        float4 v = *(const float4*)(be + (size_t)k * Hz + tid * 4);
        acc.x = fmaf(w, v.x, acc.x);
        acc.y = fmaf(w, v.y, acc.y);
        acc.z = fmaf(w, v.z, acc.z);
        acc.w = fmaf(w, v.w, acc.w);
    }
    *(float4*)&func[tid * 4] = acc;
    __syncthreads();

    float o = out_b[tid];
    for (int d = 0; d < Hz; d++)
        o = fmaf(func[d], out_w[(size_t)d * Ez + tid], o);

    float ss = o * o;
    const int lane = tid & 31, wid = tid >> 5;
#pragma unroll
    for (int off = 16; off > 0; off >>= 1)
        ss += __shfl_xor_sync(0xffffffffu, ss, off);
    if (lane == 0) red[wid] = ss;
    __syncthreads();
    float tot = 0.f;
#pragma unroll
    for (int w = 0; w < 8; w++) tot += red[w];
    float nrm = fmaxf(sqrtf(tot), 1e-12f);
    out[b * Ez + tid] = o / nrm;
}

// ======================================================================
extern "C" void kernel_launch(void* const* d_in, const int* in_sizes, int n_in,
                              void* d_out, int out_size) {
    const float* hidden = (const float*)d_in[0];
    const int* mask = (const int*)d_in[1];
    const int* bnd = (const int*)d_in[2];
    const float* tok_w1 = (const float*)d_in[3];
    const float* tok_b1 = (const float*)d_in[4];
    const float* tok_w2 = (const float*)d_in[5];
    const float* tok_b2 = (const float*)d_in[6];
    const float* blk_w1 = (const float*)d_in[7];
    const float* blk_b1 = (const float*)d_in[8];
    const float* blk_w2 = (const float*)d_in[9];
    const float* blk_b2 = (const float*)d_in[10];
    const float* out_w = (const float*)d_in[11];
    const float* out_b = (const float*)d_in[12];
    float* out = (float*)d_out;

    cudaFuncSetAttribute(k1_tok_scores,
                         cudaFuncAttributeMaxDynamicSharedMemorySize,
                         K1_SMEM_BYTES);

    k1_tok_scores<<<(Bz * Sz) / K1_BM, 512, K1_SMEM_BYTES>>>(
        hidden, tok_w1, tok_b1, tok_w2, tok_b2);
    k2_seg_stats<<<Bz * Kz, 128>>>(mask, bnd);
    k3_block_embed<<<Bz * Kz, 256>>>(hidden, mask, bnd);
    k4a_blk_partial<<<(Bz * Kz / 4) * K4_CHUNKS, 256>>>(blk_w1);
    k4b_blk_scores<<<Bz * Kz / 4, 256>>>(blk_b1, blk_w2, blk_b2);
    k5_out<<<Bz, 256>>>(out_w, out_b, out);
}

// round 16
// speedup vs baseline: 2.9776x; 1.1838x over previous
#include <cuda_runtime.h>
#include <cuda_fp16.h>
#include <math.h>
#include <stdint.h>

#define Bz 8
#define Sz 4096
#define Hz 1024
#define Ez 256
#define Kz 64
#define HQ 256
#define NEGV (-1e30f)
#define K4_CHUNKS 8
#define K4_DCH (Hz / K4_CHUNKS)   // 128

// k1 tile geometry (fp16 m16n8k16)
#define K1_BM 128
#define K1_BK 32                 // 16 half2 kpairs per tile
#define K1_APAD 20               // A row stride in words (half2): conflict-free
#define K1_BPAD 264              // B kpair stride in words: conflict-free

// ---------------- scratch (static __device__, no allocs) ----------------
__device__ float g_tok_scores[Bz * Sz];        // [B,S]
__device__ float g_mx[Bz * Kz];                // per-(b,k) max
__device__ float g_denom[Bz * Kz];             // per-(b,k) sum of exp
__device__ float g_be[(size_t)Bz * Kz * Hz];   // block_embed [B,K,H] (2 MB)
__device__ float g_blk_score[Bz * Kz];         // stage-2 scores
__device__ float g_part[(size_t)K4_CHUNKS * Bz * Kz * HQ];  // k4 split-K partials (4 MB)

__device__ __forceinline__ uint32_t h2u(__half2 h) {
    return *reinterpret_cast<uint32_t*>(&h);
}

__device__ __forceinline__ void mma_f16(float* d, const uint32_t* a, const uint32_t* b) {
    asm volatile(
        "mma.sync.aligned.m16n8k16.row.col.f32.f16.f16.f32 "
        "{%0,%1,%2,%3},{%4,%5,%6,%7},{%8,%9},{%0,%1,%2,%3};\n"
        : "+f"(d[0]), "+f"(d[1]), "+f"(d[2]), "+f"(d[3])
        : "r"(a[0]), "r"(a[1]), "r"(a[2]), "r"(a[3]), "r"(b[0]), "r"(b[1]));
}

// ======================================================================
// K1: tok_scores = tanh(h @ tok_w1 + b1) @ tok_w2 + b2   (fp16 MMA k16)
// BM=128, BN=256(full Hq), BK=32; 512 thr, 16 warps 4x4; warp tile 32x64.
// Register-staged fp32->half2 tile loads, software-pipelined.
// Epilogue fuses tanh + w2-dot + row reduction.
// ======================================================================
__global__ __launch_bounds__(512, 1)
void k1_tok_scores(const float* __restrict__ h,
                   const float* __restrict__ w1,
                   const float* __restrict__ b1,
                   const float* __restrict__ w2,
                   const float* __restrict__ b2) {
    __shared__ uint32_t As[K1_BM * K1_APAD];   // [128][20] half2 words
    __shared__ uint32_t Bs[16 * K1_BPAD];      // [16][264] half2 words
    __shared__ float rowsum[K1_BM];

    const int tid = threadIdx.x;
    const int rowbase = blockIdx.x * K1_BM;
    const int wid = tid >> 5;
    const int lane = tid & 31;
    const int warpM = wid >> 2;         // 0..3
    const int warpN = wid & 3;          // 0..3
    const int g = lane >> 2;            // 0..7
    const int c = lane & 3;             // 0..3
    const int nb = warpN * 64;

    if (tid < K1_BM) rowsum[tid] = 0.f;

    float acc[2][8][4];
#pragma unroll
    for (int mt = 0; mt < 2; mt++)
#pragma unroll
        for (int nt = 0; nt < 8; nt++)
#pragma unroll
            for (int r = 0; r < 4; r++) acc[mt][nt][r] = 0.f;

    // A map: f = tid + e*512 (0..1023) -> row=f>>3 (0..127), c4=(f&7)*4 (k float off)
    const int a_row = tid >> 3;
    const int a_c4 = (tid & 7) * 4;
    // B map: p = tid + e*512 (0..1023) -> kp=p>>6 (0..15), n4=(p&63)*4
    const int b_kp = tid >> 6;          // 0..7 (e adds 8)
    const int b_n4 = (tid & 63) * 4;

    float4 aR[2];
    float4 bR0[2], bR1[2];

#define K1_LOAD(K0)                                                            \
    do {                                                                       \
        aR[0] = *(const float4*)(h + (size_t)(rowbase + a_row) * Hz + (K0) + a_c4);          \
        aR[1] = *(const float4*)(h + (size_t)(rowbase + a_row + 64) * Hz + (K0) + a_c4);     \
        bR0[0] = *(const float4*)(w1 + (size_t)((K0) + 2 * b_kp) * HQ + b_n4);               \
        bR1[0] = *(const float4*)(w1 + (size_t)((K0) + 2 * b_kp + 1) * HQ + b_n4);           \
        bR0[1] = *(const float4*)(w1 + (size_t)((K0) + 2 * (b_kp + 8)) * HQ + b_n4);         \
        bR1[1] = *(const float4*)(w1 + (size_t)((K0) + 2 * (b_kp + 8) + 1) * HQ + b_n4);     \
    } while (0)

#define K1_STORE()                                                             \
    do {                                                                       \
        _Pragma("unroll")                                                      \
        for (int e = 0; e < 2; e++) {                                          \
            int row = a_row + e * 64;                                          \
            uint32_t w0 = h2u(__floats2half2_rn(aR[e].x, aR[e].y));            \
            uint32_t w1v = h2u(__floats2half2_rn(aR[e].z, aR[e].w));           \
            As[row * K1_APAD + a_c4 / 2] = w0;                                 \
            As[row * K1_APAD + a_c4 / 2 + 1] = w1v;                            \
        }                                                                      \
        _Pragma("unroll")                                                      \
        for (int e = 0; e < 2; e++) {                                          \
            int kp = b_kp + e * 8;                                             \
            uint32_t* dst = &Bs[kp * K1_BPAD + b_n4];                          \
            dst[0] = h2u(__floats2half2_rn(bR0[e].x, bR1[e].x));               \
            dst[1] = h2u(__floats2half2_rn(bR0[e].y, bR1[e].y));               \
            dst[2] = h2u(__floats2half2_rn(bR0[e].z, bR1[e].z));               \
            dst[3] = h2u(__floats2half2_rn(bR0[e].w, bR1[e].w));               \
        }                                                                      \
    } while (0)

    K1_LOAD(0);

    for (int it = 0; it < Hz / K1_BK; it++) {
        K1_STORE();
        __syncthreads();
        if (it < Hz / K1_BK - 1) K1_LOAD((it + 1) * K1_BK);

#pragma unroll
        for (int ks = 0; ks < 2; ks++) {
            const int kk = ks * 8;          // kpair base (16 halves = k16)
            uint32_t a[2][4], b[8][2];
#pragma unroll
            for (int mt = 0; mt < 2; mt++) {
                const int mb = warpM * 32 + mt * 16;
                a[mt][0] = As[(mb + g) * K1_APAD + kk + c];
                a[mt][1] = As[(mb + g + 8) * K1_APAD + kk + c];
                a[mt][2] = As[(mb + g) * K1_APAD + kk + c + 4];
                a[mt][3] = As[(mb + g + 8) * K1_APAD + kk + c + 4];
            }
#pragma unroll
            for (int nt = 0; nt < 8; nt++) {
                const int n = nb + nt * 8 + g;
                b[nt][0] = Bs[(kk + c) * K1_BPAD + n];
                b[nt][1] = Bs[(kk + c + 4) * K1_BPAD + n];
            }
#pragma unroll
            for (int mt = 0; mt < 2; mt++)
#pragma unroll
                for (int nt = 0; nt < 8; nt++)
                    mma_f16(acc[mt][nt], a[mt], b[nt]);
        }
        __syncthreads();   // all reads done before smem is refilled
    }
#undef K1_LOAD
#undef K1_STORE

    // epilogue: row score = sum_col tanh(acc + b1[col]) * w2[col]
#pragma unroll
    for (int mt = 0; mt < 2; mt++) {
#pragma unroll
        for (int half = 0; half < 2; half++) {
            float p = 0.f;
#pragma unroll
            for (int nt = 0; nt < 8; nt++) {
                const int col0 = nb + nt * 8 + c * 2;
                const float v0 = acc[mt][nt][half * 2 + 0] + __ldg(&b1[col0]);
                const float v1 = acc[mt][nt][half * 2 + 1] + __ldg(&b1[col0 + 1]);
                p += tanhf(v0) * __ldg(&w2[col0]) + tanhf(v1) * __ldg(&w2[col0 + 1]);
            }
            p += __shfl_xor_sync(0xffffffffu, p, 1);
            p += __shfl_xor_sync(0xffffffffu, p, 2);
            if (c == 0)
                atomicAdd(&rowsum[warpM * 32 + mt * 16 + half * 8 + g], p);
        }
    }
    __syncthreads();
    if (tid < K1_BM)
        g_tok_scores[rowbase + tid] = rowsum[tid] + b2[0];
}

// ======================================================================
// K2: per-(b,k) segment max & sum-of-exp over contiguous token range
// ======================================================================
__global__ __launch_bounds__(128)
void k2_seg_stats(const int* __restrict__ mask, const int* __restrict__ bnd) {
    const int bk = blockIdx.x;
    const int b = bk >> 6, k = bk & 63;
    int start = __ldg(&bnd[b * Kz + k]);
    int end = (k == Kz - 1) ? Sz : __ldg(&bnd[b * Kz + k + 1]);
    start = max(0, min(start, Sz));
    end = max(start, min(end, Sz));
    const float* sc = g_tok_scores + b * Sz;
    const int* mk = mask + b * Sz;
    const int tid = threadIdx.x;

    float mx = NEGV;
    for (int s = start + tid; s < end; s += 128)
        if (__ldg(&mk[s]) == 1) mx = fmaxf(mx, sc[s]);
    __shared__ float red[4];
#pragma unroll
    for (int off = 16; off > 0; off >>= 1)
        mx = fmaxf(mx, __shfl_xor_sync(0xffffffffu, mx, off));
    if ((tid & 31) == 0) red[tid >> 5] = mx;
    __syncthreads();
    mx = fmaxf(fmaxf(red[0], red[1]), fmaxf(red[2], red[3]));

    float sum = 0.f;
    for (int s = start + tid; s < end; s += 128)
        if (__ldg(&mk[s]) == 1) sum += expf(sc[s] - mx);
    __shared__ float red2[4];
#pragma unroll
    for (int off = 16; off > 0; off >>= 1)
        sum += __shfl_xor_sync(0xffffffffu, sum, off);
    if ((tid & 31) == 0) red2[tid >> 5] = sum;
    __syncthreads();
    if (tid == 0) {
        g_mx[bk] = mx;
        g_denom[bk] = red2[0] + red2[1] + red2[2] + red2[3];
    }
}

// ======================================================================
// K3: block_embed[b,k,:] = sum_s w[s] * h[b,s,:]   (segmented)
// ======================================================================
__global__ __launch_bounds__(256)
void k3_block_embed(const float* __restrict__ h,
                    const int* __restrict__ mask,
                    const int* __restrict__ bnd) {
    const int bk = blockIdx.x;
    const int b = bk >> 6, k = bk & 63;
    int start = __ldg(&bnd[b * Kz + k]);
    int end = (k == Kz - 1) ? Sz : __ldg(&bnd[b * Kz + k + 1]);
    start = max(0, min(start, Sz));
    end = max(start, min(end, Sz));
    const float mx = g_mx[bk];
    const float den = g_denom[bk];
    const float inv = (den > 0.f) ? 1.f / fmaxf(den, 1e-30f) : 0.f;
    const int tid = threadIdx.x;

    const float* sc = g_tok_scores + b * Sz;
    const int* mk = mask + b * Sz;
    const float* hb = h + (size_t)b * Sz * Hz;

    __shared__ float wts[128];
    float4 acc = make_float4(0.f, 0.f, 0.f, 0.f);

    for (int cs = start; cs < end; cs += 128) {
        const int n = min(128, end - cs);
        if (tid < 128) {
            int s = cs + tid;
            float w = 0.f;
            if (s < end && __ldg(&mk[s]) == 1) w = expf(sc[s] - mx) * inv;
            wts[tid] = w;
        }
        __syncthreads();
        for (int i = 0; i < n; i++) {
            float w = wts[i];
            if (w != 0.f) {
                float4 hv = *(const float4*)(hb + (size_t)(cs + i) * Hz + tid * 4);
                acc.x = fmaf(w, hv.x, acc.x);
                acc.y = fmaf(w, hv.y, acc.y);
                acc.z = fmaf(w, hv.z, acc.z);
                acc.w = fmaf(w, hv.w, acc.w);
            }
        }
        __syncthreads();
    }
    *(float4*)(g_be + (size_t)bk * Hz + tid * 4) = acc;
}

// ======================================================================
// K4a: split-K partial GEMM for blk pre-activations.
// ======================================================================
__global__ __launch_bounds__(256)
void k4a_blk_partial(const float* __restrict__ w1) {
    const int group = blockIdx.x >> 3;       // 0..127
    const int chunk = blockIdx.x & 7;        // 0..7
    const int bk0 = group * 4;
    const int d0 = chunk * K4_DCH;
    const int j = threadIdx.x;

    __shared__ float bes[4][K4_DCH];         // 2 KB
#pragma unroll
    for (int e = 0; e < 2; e++) {
        int idx = j + e * 256;               // 0..511
        int r = idx >> 7, d = idx & 127;
        bes[r][d] = g_be[(size_t)(bk0 + r) * Hz + d0 + d];
    }
    __syncthreads();

    float a0 = 0.f, a1 = 0.f, a2 = 0.f, a3 = 0.f;
    const float* w1c = w1 + (size_t)d0 * HQ + j;
#pragma unroll 8
    for (int dd = 0; dd < K4_DCH; dd++) {
        float w = __ldg(w1c + (size_t)dd * HQ);
        a0 = fmaf(bes[0][dd], w, a0);
        a1 = fmaf(bes[1][dd], w, a1);
        a2 = fmaf(bes[2][dd], w, a2);
        a3 = fmaf(bes[3][dd], w, a3);
    }
    float* p = g_part + (size_t)chunk * (Bz * Kz * HQ) + (size_t)bk0 * HQ + j;
    p[0 * HQ] = a0;
    p[1 * HQ] = a1;
    p[2 * HQ] = a2;
    p[3 * HQ] = a3;
}

// ======================================================================
// K4b: combine partials -> tanh -> w2 dot -> blk score (+ validity)
// ======================================================================
__global__ __launch_bounds__(256)
void k4b_blk_scores(const float* __restrict__ b1,
                    const float* __restrict__ w2,
                    const float* __restrict__ b2) {
    const int bk0 = blockIdx.x * 4;
    const int j = threadIdx.x;
    const float b1j = b1[j], w2j = w2[j];

    float v[4];
#pragma unroll
    for (int r = 0; r < 4; r++) {
        float a = 0.f;
#pragma unroll
        for (int c = 0; c < K4_CHUNKS; c++)
            a += g_part[(size_t)c * (Bz * Kz * HQ) + (size_t)(bk0 + r) * HQ + j];
        v[r] = tanhf(a + b1j) * w2j;
    }

    __shared__ float red[4][8];
    const int lane = j & 31, wid = j >> 5;
#pragma unroll
    for (int r = 0; r < 4; r++) {
        float x = v[r];
#pragma unroll
        for (int off = 16; off > 0; off >>= 1)
            x += __shfl_xor_sync(0xffffffffu, x, off);
        if (lane == 0) red[r][wid] = x;
    }
    __syncthreads();
    if (j < 4) {
        float s = 0.f;
#pragma unroll
        for (int w = 0; w < 8; w++) s += red[j][w];
        s += b2[0];
        int bk = bk0 + j;
        g_blk_score[bk] = (g_denom[bk] > 0.f) ? s : NEGV;
    }
}

// ======================================================================
// K5: per batch: softmax over blocks -> func -> out proj -> L2 normalize
// ======================================================================
__global__ __launch_bounds__(256)
void k5_out(const float* __restrict__ out_w,
            const float* __restrict__ out_b,
            float* __restrict__ out) {
    const int b = blockIdx.x;
    const int tid = threadIdx.x;
    __shared__ float bw[Kz];
    __shared__ float func[Hz];
    __shared__ float red[8];

    if (tid == 0) {
        float mx = NEGV;
        for (int k = 0; k < Kz; k++) mx = fmaxf(mx, g_blk_score[b * Kz + k]);
        float s = 0.f;
        for (int k = 0; k < Kz; k++) {
            float e = expf(g_blk_score[b * Kz + k] - mx);
            bw[k] = e;
            s += e;
        }
        float inv = 1.f / s;
        for (int k = 0; k < Kz; k++) bw[k] *= inv;
    }
    __syncthreads();

    const float* be = g_be + (size_t)b * Kz * Hz;
    float4 acc = make_float4(0.f, 0.f, 0.f, 0.f);
    for (int k = 0; k < Kz; k++) {
        float w = bw[k];
        float4 v = *(const float4*)(be + (size_t)k * Hz + tid * 4);
        acc.x = fmaf(w, v.x, acc.x);
        acc.y = fmaf(w, v.y, acc.y);
        acc.z = fmaf(w, v.z, acc.z);
        acc.w = fmaf(w, v.w, acc.w);
    }
    *(float4*)&func[tid * 4] = acc;
    __syncthreads();

    float o = out_b[tid];
    for (int d = 0; d < Hz; d++)
        o = fmaf(func[d], out_w[(size_t)d * Ez + tid], o);

    float ss = o * o;
    const int lane = tid & 31, wid = tid >> 5;
#pragma unroll
    for (int off = 16; off > 0; off >>= 1)
        ss += __shfl_xor_sync(0xffffffffu, ss, off);
    if (lane == 0) red[wid] = ss;
    __syncthreads();
    float tot = 0.f;
#pragma unroll
    for (int w = 0; w < 8; w++) tot += red[w];
    float nrm = fmaxf(sqrtf(tot), 1e-12f);
    out[b * Ez + tid] = o / nrm;
}

// ======================================================================
extern "C" void kernel_launch(void* const* d_in, const int* in_sizes, int n_in,
                              void* d_out, int out_size) {
    const float* hidden = (const float*)d_in[0];
    const int* mask = (const int*)d_in[1];
    const int* bnd = (const int*)d_in[2];
    const float* tok_w1 = (const float*)d_in[3];
    const float* tok_b1 = (const float*)d_in[4];
    const float* tok_w2 = (const float*)d_in[5];
    const float* tok_b2 = (const float*)d_in[6];
    const float* blk_w1 = (const float*)d_in[7];
    const float* blk_b1 = (const float*)d_in[8];
    const float* blk_w2 = (const float*)d_in[9];
    const float* blk_b2 = (const float*)d_in[10];
    const float* out_w = (const float*)d_in[11];
    const float* out_b = (const float*)d_in[12];
    float* out = (float*)d_out;

    k1_tok_scores<<<(Bz * Sz) / K1_BM, 512>>>(hidden, tok_w1, tok_b1, tok_w2, tok_b2);
    k2_seg_stats<<<Bz * Kz, 128>>>(mask, bnd);
    k3_block_embed<<<Bz * Kz, 256>>>(hidden, mask, bnd);
    k4a_blk_partial<<<(Bz * Kz / 4) * K4_CHUNKS, 256>>>(blk_w1);
    k4b_blk_scores<<<Bz * Kz / 4, 256>>>(blk_b1, blk_w2, blk_b2);
    k5_out<<<Bz, 256>>>(out_w, out_b, out);
}